// round 16
// baseline (speedup 1.0000x reference)
#include <cuda_runtime.h>
#include <cuda_fp16.h>
#include <math.h>

#define NT 131072
#define ET 2097152
#define NP 24576
#define EP 196608
#define NTOT (NT + NP)
#define D_IN 480
#define HID 128
#define NHEAD 4
#define CDIM 32
#define NLAYERS 3
#define BATCH 2048
#define LN_EPS 1e-5f

// ---------------- scratch (device globals; no allocations allowed) ----------------
__device__ float  g_h[(size_t)NTOT * HID];    // current node features (combined graph, fp32)
__device__ __half g_hp[(size_t)NTOT * HID];   // projected features (per layer, fp16)
__device__ float  g_ssrc[NTOT * NHEAD];
__device__ float  g_sdst[NTOT * NHEAD];
__device__ int    g_rowptr[NTOT + 1];
__device__ int    g_cursor[NTOT];             // also used as degree histogram
__device__ int    g_srcsorted[ET + EP + NTOT + 8];  // +8 pad: branch-free over-read (zero-init = node 0)
__device__ int    g_batch[NTOT];              // combined batch ids (pep + BATCH)
__device__ float  g_pool[2 * BATCH * HID];
__device__ float  g_cnt[2 * BATCH];

// ---------------- mma + cp.async helpers ----------------
__device__ __forceinline__ void mma_tf32(float* d, const unsigned* a, const unsigned* b) {
    asm volatile(
        "mma.sync.aligned.m16n8k8.row.col.f32.tf32.tf32.f32 "
        "{%0,%1,%2,%3}, {%4,%5,%6,%7}, {%8,%9}, {%0,%1,%2,%3};"
        : "+f"(d[0]), "+f"(d[1]), "+f"(d[2]), "+f"(d[3])
        : "r"(a[0]), "r"(a[1]), "r"(a[2]), "r"(a[3]), "r"(b[0]), "r"(b[1]));
}
__device__ __forceinline__ void cp16(unsigned smem, const void* g) {
    asm volatile("cp.async.cg.shared.global [%0], [%1], 16;" :: "r"(smem), "l"(g));
}
__device__ __forceinline__ void cp_commit() {
    asm volatile("cp.async.commit_group;" ::: "memory");
}
__device__ __forceinline__ void cp_wait1() {
    asm volatile("cp.async.wait_group 1;" ::: "memory");
}
__device__ __forceinline__ unsigned s2u(const void* p) {
    return (unsigned)__cvta_generic_to_shared(p);
}

// ---------------- CSR build (combined graph, fused over both subgraphs) ----------------
__global__ void k_hist2(const int* __restrict__ dstA, const int* __restrict__ dstB,
                        int* __restrict__ deg, int EA, int EB, int offB) {
    int i = blockIdx.x * blockDim.x + threadIdx.x;
    if (i < EA) atomicAdd(&deg[dstA[i]], 1);
    else if (i < EA + EB) atomicAdd(&deg[dstB[i - EA] + offB], 1);
}

// single-block exclusive scan of (deg[i] + 1) over n entries -> rowptr
__global__ void k_scan(const int* __restrict__ deg, int* __restrict__ rowptr, int n) {
    __shared__ int ss[1024];
    int tid = threadIdx.x;
    int chunk = (n + 1023) >> 10;
    int s = tid * chunk;
    int e = min(s + chunk, n);
    int local = 0;
    for (int i = s; i < e; i++) local += deg[i] + 1;
    ss[tid] = local;
    __syncthreads();
    for (int d = 1; d < 1024; d <<= 1) {
        int t = (tid >= d) ? ss[tid - d] : 0;
        __syncthreads();
        ss[tid] += t;
        __syncthreads();
    }
    int run = ss[tid] - local; // exclusive prefix
    for (int i = s; i < e; i++) { rowptr[i] = run; run += deg[i] + 1; }
    if (tid == 0) rowptr[n] = ss[1023];
}

// scatter edges + self loops; also emits the combined batch vector and the
// end-sentinel for the aggregate's branch-free over-read.
__global__ void k_scatter2(const int* __restrict__ srcA, const int* __restrict__ dstA,
                           const int* __restrict__ srcB, const int* __restrict__ dstB,
                           const int* __restrict__ rowptr, int* __restrict__ cursor,
                           int* __restrict__ outsrc,
                           const int* __restrict__ batA, const int* __restrict__ batB_in,
                           int* __restrict__ batout,
                           int EA, int EB, int offB, int Ncomb) {
    int i = blockIdx.x * blockDim.x + threadIdx.x;
    if (i >= EA + EB + Ncomb) return;
    if (i == 0) outsrc[EA + EB + Ncomb] = 0;   // sentinel (valid node id)
    int s, d;
    if (i < EA)            { s = srcA[i];            d = dstA[i]; }
    else if (i < EA + EB)  { int j = i - EA; s = srcB[j] + offB; d = dstB[j] + offB; }
    else {
        int n = i - EA - EB;                   // self loop for node n
        s = d = n;
        batout[n] = (n < offB) ? batA[n] : batB_in[n - offB] + BATCH;
    }
    int pos = rowptr[d] + atomicAdd(&cursor[d], 1);
    outsrc[pos] = s;
}

// ---------------- TF32 tensor-core GEMM, 3-stage cp.async pipeline ----------------
// MODE 1: C fp32, relu(.+bias). MODE 2: C fp16 (Ch) + fused ssrc/sdst dots.
// 128x128 CTA tile, 8 warps (2x4), warp tile 64x32, mma.sync m16n8k8 tf32.
// A smem [m][k] stride 20; B smem [k][n] stride 132. Raw fp32 bits as tf32.
template <int MODE>
__global__ void __launch_bounds__(256, 2) k_gemm(const float* __restrict__ A,
                                                 const float* __restrict__ W,
                                                 const float* __restrict__ bias,
                                                 float* __restrict__ C,
                                                 __half* __restrict__ Ch, int K,
                                                 const float* __restrict__ asrc,
                                                 const float* __restrict__ adst,
                                                 float* __restrict__ ssrc,
                                                 float* __restrict__ sdst) {
    __shared__ unsigned As[3][128][20];   // [m][k], pad 20
    __shared__ unsigned Bs[3][16][132];   // [k][n], pad 132
    int tid = threadIdx.x;
    int m0 = blockIdx.x * 128;
    int warp = tid >> 5, lane = tid & 31;
    int wm = (warp >> 2) << 6;   // 0 or 64
    int wn = (warp & 3) << 5;    // 0,32,64,96
    int qid = lane >> 2;         // 0..7
    int qlane = lane & 3;        // 0..3

    int a_row = tid >> 1, a_c8 = (tid & 1) << 3;
    int b_row = tid >> 4, b_c8 = (tid & 15) << 3;

    float acc[16][4];
#pragma unroll
    for (int i = 0; i < 16; i++)
#pragma unroll
        for (int j = 0; j < 4; j++) acc[i][j] = 0.f;

    int ntiles = K >> 4;

    // prologue: tiles 0,1 -> bufs 0,1
#pragma unroll
    for (int pt = 0; pt < 2; pt++) {
        if (pt < ntiles) {
            int k0 = pt << 4;
            const float* ga = &A[(size_t)(m0 + a_row) * K + k0 + a_c8];
            cp16(s2u(&As[pt][a_row][a_c8]), ga);
            cp16(s2u(&As[pt][a_row][a_c8 + 4]), ga + 4);
            const float* gb = &W[(size_t)(k0 + b_row) * 128 + b_c8];
            cp16(s2u(&Bs[pt][b_row][b_c8]), gb);
            cp16(s2u(&Bs[pt][b_row][b_c8 + 4]), gb + 4);
        }
        cp_commit();
    }

    for (int t = 0; t < ntiles; t++) {
        cp_wait1();          // tile t's copy complete (<=1 group pending)
        __syncthreads();     // also guards reuse of buf[(t+2)%3]
        int buf = t % 3;
        if (t + 2 < ntiles) {
            int nb = (t + 2) % 3;
            int k0 = (t + 2) << 4;
            const float* ga = &A[(size_t)(m0 + a_row) * K + k0 + a_c8];
            cp16(s2u(&As[nb][a_row][a_c8]), ga);
            cp16(s2u(&As[nb][a_row][a_c8 + 4]), ga + 4);
            const float* gb = &W[(size_t)(k0 + b_row) * 128 + b_c8];
            cp16(s2u(&Bs[nb][b_row][b_c8]), gb);
            cp16(s2u(&Bs[nb][b_row][b_c8 + 4]), gb + 4);
            cp_commit();
        } else {
            cp_commit();     // keep group count in step for wait_group 1
        }
#pragma unroll
        for (int ks = 0; ks < 2; ks++) {
            int kb = ks << 3;
            unsigned bf[4][2], af[4][4];
#pragma unroll
            for (int nt = 0; nt < 4; nt++) {
                int n = wn + (nt << 3) + qid;
                bf[nt][0] = Bs[buf][kb + qlane][n];
                bf[nt][1] = Bs[buf][kb + qlane + 4][n];
            }
#pragma unroll
            for (int mt = 0; mt < 4; mt++) {
                int m = wm + (mt << 4) + qid;
                af[mt][0] = As[buf][m][kb + qlane];
                af[mt][1] = As[buf][m + 8][kb + qlane];
                af[mt][2] = As[buf][m][kb + qlane + 4];
                af[mt][3] = As[buf][m + 8][kb + qlane + 4];
            }
#pragma unroll
            for (int mt = 0; mt < 4; mt++)
#pragma unroll
                for (int nt = 0; nt < 4; nt++)
                    mma_tf32(acc[mt * 4 + nt], af[mt], bf[nt]);
        }
    }

    // epilogue: store C (+ optional fused scores)
#pragma unroll
    for (int mt = 0; mt < 4; mt++) {
        float psrc0 = 0.f, psrc1 = 0.f, pdst0 = 0.f, pdst1 = 0.f;
#pragma unroll
        for (int nt = 0; nt < 4; nt++) {
            float* c = acc[mt * 4 + nt];
            int row0 = m0 + wm + (mt << 4) + qid;
            int col = wn + (nt << 3) + (qlane << 1);
            float b0 = 0.f, b1 = 0.f;
            if (MODE == 1) { b0 = bias[col]; b1 = bias[col + 1]; }
            float2 v0, v1;
            v0.x = c[0]; v0.y = c[1];
            v1.x = c[2]; v1.y = c[3];
            if (MODE == 1) {
                v0.x = fmaxf(v0.x + b0, 0.f); v0.y = fmaxf(v0.y + b1, 0.f);
                v1.x = fmaxf(v1.x + b0, 0.f); v1.y = fmaxf(v1.y + b1, 0.f);
            }
            if (MODE == 2) {
                float a0 = asrc[col], a1 = asrc[col + 1];
                float d0 = adst[col], d1 = adst[col + 1];
                psrc0 += v0.x * a0 + v0.y * a1;
                psrc1 += v1.x * a0 + v1.y * a1;
                pdst0 += v0.x * d0 + v0.y * d1;
                pdst1 += v1.x * d0 + v1.y * d1;
                // fp16 store for the aggregate gather
                __half2 h0 = __float22half2_rn(v0);
                __half2 h1 = __float22half2_rn(v1);
                *(__half2*)&Ch[(size_t)row0 * 128 + col] = h0;
                *(__half2*)&Ch[(size_t)(row0 + 8) * 128 + col] = h1;
            } else {
                *(float2*)&C[(size_t)row0 * 128 + col] = v0;
                *(float2*)&C[(size_t)(row0 + 8) * 128 + col] = v1;
            }
        }
        if (MODE == 2) {
            // reduce over qlane group (lanes qid*4 .. qid*4+3)
#pragma unroll
            for (int o = 2; o; o >>= 1) {
                psrc0 += __shfl_down_sync(0xffffffffu, psrc0, o, 4);
                psrc1 += __shfl_down_sync(0xffffffffu, psrc1, o, 4);
                pdst0 += __shfl_down_sync(0xffffffffu, pdst0, o, 4);
                pdst1 += __shfl_down_sync(0xffffffffu, pdst1, o, 4);
            }
            if (qlane == 0) {
                int row0 = m0 + wm + (mt << 4) + qid;
                int head = warp & 3;
                ssrc[row0 * 4 + head] = psrc0;
                sdst[row0 * 4 + head] = pdst0;
                ssrc[(row0 + 8) * 4 + head] = psrc1;
                sdst[(row0 + 8) * 4 + head] = pdst1;
            }
        }
    }
}

// ---------------- fused softmax + aggregate + bias + LN + relu + residual (+pool) ----------------
// One warp per node, TWO edges per iteration: half-warp h (lanes 16h..16h+15)
// handles edge e+h; lane covers 8 columns via one LDG.128 (uint4 of 8 fp16).
// Branch-free depth-2 pipeline; srcs over-read safe (pad zero-init = node 0);
// trailing odd edge neutralized by zeroing p. Halves combined by shfl_xor(16).
template <bool LAST>
__global__ void __launch_bounds__(256) k_aggregate(
        const __half* __restrict__ hp, const float* __restrict__ ssrc,
        const float* __restrict__ sdst, const int* __restrict__ rowptr,
        const int* __restrict__ srcs, const float* __restrict__ bias,
        const float* __restrict__ gam, const float* __restrict__ bet,
        float* __restrict__ h, const int* __restrict__ batch,
        float* __restrict__ pool, float* __restrict__ cnt, int N) {
    int gw = (blockIdx.x * blockDim.x + threadIdx.x) >> 5;
    int lane = threadIdx.x & 31;
    if (gw >= N) return;
    int half = lane >> 4;                // 0/1: which edge of the pair
    int sub  = lane & 15;                // 0..15: column group
    int hh   = sub >> 2;                 // head of this lane's 8 columns
    int c0   = sub << 3;                 // column base (8 cols)
    float sd = __ldg(&sdst[gw * 4 + hh]);
    int e0 = rowptr[gw], e1 = rowptr[gw + 1];

    float z = 0.f;
    float acc[8];
#pragma unroll
    for (int j = 0; j < 8; j++) acc[j] = 0.f;

    // depth-2 pipeline over edge pairs (degree >= 1 always: self loop).
    // my edge for iteration e is (e + half); over-reads up to e1+2 land in
    // the next row's edges or the zero-initialized pad -> valid node ids.
    int s_cur = __ldg(&srcs[e0 + half]);
    float sv_cur = __ldg(&ssrc[s_cur * 4 + hh]);
    uint4 hv_cur = __ldg((const uint4*)(hp + (size_t)s_cur * HID + c0));

    for (int e = e0; e < e1; e += 2) {
        int s_nxt = __ldg(&srcs[e + 2 + half]);
        float sv_nxt = __ldg(&ssrc[s_nxt * 4 + hh]);
        uint4 hv_nxt = __ldg((const uint4*)(hp + (size_t)s_nxt * HID + c0));

        float ev = sv_cur + sd;
        ev = fmaxf(ev, 0.2f * ev);               // leaky_relu, branch-free
        float p = __expf(ev);
        if (e + half >= e1) p = 0.f;             // trailing odd edge -> no-op
        z += p;
        float2 f0 = __half22float2(*(const __half2*)&hv_cur.x);
        float2 f1 = __half22float2(*(const __half2*)&hv_cur.y);
        float2 f2 = __half22float2(*(const __half2*)&hv_cur.z);
        float2 f3 = __half22float2(*(const __half2*)&hv_cur.w);
        acc[0] = fmaf(p, f0.x, acc[0]);
        acc[1] = fmaf(p, f0.y, acc[1]);
        acc[2] = fmaf(p, f1.x, acc[2]);
        acc[3] = fmaf(p, f1.y, acc[3]);
        acc[4] = fmaf(p, f2.x, acc[4]);
        acc[5] = fmaf(p, f2.y, acc[5]);
        acc[6] = fmaf(p, f3.x, acc[6]);
        acc[7] = fmaf(p, f3.y, acc[7]);
        s_cur = s_nxt; sv_cur = sv_nxt; hv_cur = hv_nxt;
    }

    // combine the two half-warps: both halves then hold the full sums
    z += __shfl_xor_sync(0xffffffffu, z, 16);
#pragma unroll
    for (int j = 0; j < 8; j++) acc[j] += __shfl_xor_sync(0xffffffffu, acc[j], 16);

    float inv = 1.f / z;
    float4 b01 = *(const float4*)&bias[c0];
    float4 b23 = *(const float4*)&bias[c0 + 4];
    float r[8];
    r[0] = acc[0] * inv + b01.x;
    r[1] = acc[1] * inv + b01.y;
    r[2] = acc[2] * inv + b01.z;
    r[3] = acc[3] * inv + b01.w;
    r[4] = acc[4] * inv + b23.x;
    r[5] = acc[5] * inv + b23.y;
    r[6] = acc[6] * inv + b23.z;
    r[7] = acc[7] * inv + b23.w;

    // layernorm across the row: data lives on 16 lanes x 8 cols (identical in
    // both halves), so reduce with xor offsets 8..1 (stays within each half)
    float s = 0.f;
#pragma unroll
    for (int j = 0; j < 8; j++) s += r[j];
#pragma unroll
    for (int o = 8; o; o >>= 1) s += __shfl_xor_sync(0xffffffffu, s, o);
    float mu = s * (1.f / 128.f);
    float var = 0.f;
#pragma unroll
    for (int j = 0; j < 8; j++) { float d = r[j] - mu; var = fmaf(d, d, var); }
#pragma unroll
    for (int o = 8; o; o >>= 1) var += __shfl_xor_sync(0xffffffffu, var, o);
    float rinv = rsqrtf(var * (1.f / 128.f) + LN_EPS);

    if (half == 0) {
        float4 g01 = *(const float4*)&gam[c0];
        float4 g23 = *(const float4*)&gam[c0 + 4];
        float4 t01 = *(const float4*)&bet[c0];
        float4 t23 = *(const float4*)&bet[c0 + 4];
        float4 h01 = *(const float4*)&h[(size_t)gw * HID + c0];
        float4 h23 = *(const float4*)&h[(size_t)gw * HID + c0 + 4];
        float4 n01, n23;
        n01.x = h01.x + fmaxf((r[0] - mu) * rinv * g01.x + t01.x, 0.f);
        n01.y = h01.y + fmaxf((r[1] - mu) * rinv * g01.y + t01.y, 0.f);
        n01.z = h01.z + fmaxf((r[2] - mu) * rinv * g01.z + t01.z, 0.f);
        n01.w = h01.w + fmaxf((r[3] - mu) * rinv * g01.w + t01.w, 0.f);
        n23.x = h23.x + fmaxf((r[4] - mu) * rinv * g23.x + t23.x, 0.f);
        n23.y = h23.y + fmaxf((r[5] - mu) * rinv * g23.y + t23.y, 0.f);
        n23.z = h23.z + fmaxf((r[6] - mu) * rinv * g23.z + t23.z, 0.f);
        n23.w = h23.w + fmaxf((r[7] - mu) * rinv * g23.w + t23.w, 0.f);
        *(float4*)&h[(size_t)gw * HID + c0] = n01;
        *(float4*)&h[(size_t)gw * HID + c0 + 4] = n23;

        if (LAST) {
            int b = __ldg(&batch[gw]);
            float* pr = pool + (size_t)b * HID + c0;
            atomicAdd(pr + 0, n01.x);
            atomicAdd(pr + 1, n01.y);
            atomicAdd(pr + 2, n01.z);
            atomicAdd(pr + 3, n01.w);
            atomicAdd(pr + 4, n23.x);
            atomicAdd(pr + 5, n23.y);
            atomicAdd(pr + 6, n23.z);
            atomicAdd(pr + 7, n23.w);
            if (lane == 0) atomicAdd(&cnt[b], 1.f);
        }
    }
}

// ---------------- MLP head: one block per batch row ----------------
__global__ void __launch_bounds__(128) k_mlp(const float* __restrict__ poolA, const float* __restrict__ cntA,
                                             const float* __restrict__ poolB, const float* __restrict__ cntB,
                                             const float* __restrict__ Wc1, const float* __restrict__ bc1,
                                             const float* __restrict__ Wc2, const float* __restrict__ bc2,
                                             const float* __restrict__ Wc3, const float* __restrict__ bc3,
                                             float* __restrict__ out) {
    __shared__ float z[256];
    __shared__ float o1[128];
    __shared__ float o2[64];
    int b = blockIdx.x, t = threadIdx.x;
    float ca = fmaxf(cntA[b], 1.f), cb = fmaxf(cntB[b], 1.f);
    z[t]       = poolA[(size_t)b * HID + t] / ca;
    z[t + 128] = poolB[(size_t)b * HID + t] / cb;
    __syncthreads();
    float a1 = bc1[t];
#pragma unroll 8
    for (int i = 0; i < 256; i++) a1 = fmaf(z[i], Wc1[i * 128 + t], a1);
    o1[t] = fmaxf(a1, 0.f);
    __syncthreads();
    if (t < 64) {
        float a2 = bc2[t];
#pragma unroll 8
        for (int i = 0; i < 128; i++) a2 = fmaf(o1[i], Wc2[i * 64 + t], a2);
        o2[t] = fmaxf(a2, 0.f);
    }
    __syncthreads();
    if (t < 32) {
        float a3 = fmaf(o2[t], Wc3[t], o2[t + 32] * Wc3[t + 32]);
#pragma unroll
        for (int o = 16; o; o >>= 1) a3 += __shfl_xor_sync(0xffffffffu, a3, o);
        if (t == 0) out[b] = 1.f / (1.f + __expf(-(a3 + bc3[0])));
    }
}

extern "C" void kernel_launch(void* const* d_in, const int* in_sizes, int n_in,
                              void* d_out, int out_size) {
    const float* tcr_x    = (const float*)d_in[0];
    const int*   tcr_ei   = (const int*)d_in[1];
    const int*   tcr_bat  = (const int*)d_in[2];
    const float* pep_x    = (const float*)d_in[3];
    const int*   pep_ei   = (const int*)d_in[4];
    const int*   pep_bat  = (const int*)d_in[5];
    const float* W_in     = (const float*)d_in[6];
    const float* b_in     = (const float*)d_in[7];
    const float* Wg       = (const float*)d_in[8];
    const float* bg       = (const float*)d_in[9];
    const float* att_src  = (const float*)d_in[10];
    const float* att_dst  = (const float*)d_in[11];
    const float* ln_g     = (const float*)d_in[12];
    const float* ln_b     = (const float*)d_in[13];
    const float* Wc1      = (const float*)d_in[14];
    const float* bc1      = (const float*)d_in[15];
    const float* Wc2      = (const float*)d_in[16];
    const float* bc2      = (const float*)d_in[17];
    const float* Wc3      = (const float*)d_in[18];
    const float* bc3      = (const float*)d_in[19];
    float* out = (float*)d_out;

    int Ntc = in_sizes[2];          // 131072
    int Etc = in_sizes[1] / 2;      // 2097152
    int Npp = in_sizes[5];          // 24576
    int Epp = in_sizes[4] / 2;      // 196608
    int Ncomb = Ntc + Npp;          // 155648

    float *hB, *ssrcB, *sdstB, *poolB, *cntB;
    __half* hpB;
    int *rpB, *curB, *ssB, *batB;
    cudaGetSymbolAddress((void**)&hB, g_h);
    cudaGetSymbolAddress((void**)&hpB, g_hp);
    cudaGetSymbolAddress((void**)&ssrcB, g_ssrc);
    cudaGetSymbolAddress((void**)&sdstB, g_sdst);
    cudaGetSymbolAddress((void**)&rpB, g_rowptr);
    cudaGetSymbolAddress((void**)&curB, g_cursor);
    cudaGetSymbolAddress((void**)&ssB, g_srcsorted);
    cudaGetSymbolAddress((void**)&batB, g_batch);
    cudaGetSymbolAddress((void**)&poolB, g_pool);
    cudaGetSymbolAddress((void**)&cntB, g_cnt);

    cudaMemsetAsync(poolB, 0, 2 * BATCH * HID * sizeof(float));
    cudaMemsetAsync(cntB, 0, 2 * BATCH * sizeof(float));

    // ---- combined CSR build (fused hist + fused scatter incl. batch concat) ----
    cudaMemsetAsync(curB, 0, (size_t)Ncomb * sizeof(int));
    k_hist2<<<(Etc + Epp + 255) / 256, 256>>>(tcr_ei + Etc, pep_ei + Epp, curB, Etc, Epp, Ntc);
    k_scan<<<1, 1024>>>(curB, rpB, Ncomb);
    cudaMemsetAsync(curB, 0, (size_t)Ncomb * sizeof(int));
    k_scatter2<<<(Etc + Epp + Ncomb + 255) / 256, 256>>>(tcr_ei, tcr_ei + Etc,
                                                         pep_ei, pep_ei + Epp,
                                                         rpB, curB, ssB,
                                                         tcr_bat, pep_bat, batB,
                                                         Etc, Epp, Ntc, Ncomb);

    // ---- input projections (separate launches) ----
    k_gemm<1><<<Ntc / 128, 256>>>(tcr_x, W_in, b_in, hB, nullptr, D_IN,
                                  nullptr, nullptr, nullptr, nullptr);
    k_gemm<1><<<Npp / 128, 256>>>(pep_x, W_in, b_in, hB + (size_t)Ntc * HID, nullptr, D_IN,
                                  nullptr, nullptr, nullptr, nullptr);

    // ---- GAT layers on the combined graph ----
    for (int l = 0; l < NLAYERS; l++) {
        k_gemm<2><<<Ncomb / 128, 256>>>(hB, Wg + (size_t)l * HID * HID, nullptr,
                                        nullptr, hpB, HID,
                                        att_src + l * HID, att_dst + l * HID, ssrcB, sdstB);
        if (l == NLAYERS - 1)
            k_aggregate<true><<<Ncomb / 8, 256>>>(hpB, ssrcB, sdstB, rpB, ssB,
                                                  bg + l * HID, ln_g + l * HID, ln_b + l * HID,
                                                  hB, batB, poolB, cntB, Ncomb);
        else
            k_aggregate<false><<<Ncomb / 8, 256>>>(hpB, ssrcB, sdstB, rpB, ssB,
                                                   bg + l * HID, ln_g + l * HID, ln_b + l * HID,
                                                   hB, nullptr, nullptr, nullptr, Ncomb);
    }

    // ---- MLP head ----
    k_mlp<<<BATCH, 128>>>(poolB, cntB, poolB + BATCH * HID, cntB + BATCH,
                          Wc1, bc1, Wc2, bc2, Wc3, bc3, out);
}

// round 17
// speedup vs baseline: 1.3595x; 1.3595x over previous
#include <cuda_runtime.h>
#include <cuda_fp16.h>
#include <math.h>

#define NT 131072
#define ET 2097152
#define NP 24576
#define EP 196608
#define NTOT (NT + NP)
#define D_IN 480
#define HID 128
#define NHEAD 4
#define CDIM 32
#define NLAYERS 3
#define BATCH 2048
#define LN_EPS 1e-5f

// ---------------- scratch (device globals; no allocations allowed) ----------------
__device__ float  g_h[(size_t)NTOT * HID];    // current node features (combined graph, fp32)
__device__ __half g_hp[(size_t)NTOT * HID];   // projected features (per layer, fp16)
__device__ float  g_ssrc[NTOT * NHEAD];
__device__ float  g_sdst[NTOT * NHEAD];
__device__ int    g_rowptr[NTOT + 1];
__device__ int    g_cursor[NTOT];             // also used as degree histogram
__device__ int    g_srcsorted[ET + EP + NTOT + 8];  // +8 pad: branch-free over-read
__device__ int    g_batch[NTOT];              // combined batch ids (pep + BATCH)
__device__ int    g_bsum[1024];               // block sums for two-level scan
__device__ float  g_pool[2 * BATCH * HID];
__device__ float  g_cnt[2 * BATCH];

// ---------------- mma + cp.async helpers ----------------
__device__ __forceinline__ void mma_tf32(float* d, const unsigned* a, const unsigned* b) {
    asm volatile(
        "mma.sync.aligned.m16n8k8.row.col.f32.tf32.tf32.f32 "
        "{%0,%1,%2,%3}, {%4,%5,%6,%7}, {%8,%9}, {%0,%1,%2,%3};"
        : "+f"(d[0]), "+f"(d[1]), "+f"(d[2]), "+f"(d[3])
        : "r"(a[0]), "r"(a[1]), "r"(a[2]), "r"(a[3]), "r"(b[0]), "r"(b[1]));
}
__device__ __forceinline__ void cp16(unsigned smem, const void* g) {
    asm volatile("cp.async.cg.shared.global [%0], [%1], 16;" :: "r"(smem), "l"(g));
}
__device__ __forceinline__ void cp_commit() {
    asm volatile("cp.async.commit_group;" ::: "memory");
}
__device__ __forceinline__ void cp_wait1() {
    asm volatile("cp.async.wait_group 1;" ::: "memory");
}
__device__ __forceinline__ unsigned s2u(const void* p) {
    return (unsigned)__cvta_generic_to_shared(p);
}

// ---------------- CSR build (combined graph, fused over both subgraphs) ----------------
__global__ void k_hist2(const int* __restrict__ dstA, const int* __restrict__ dstB,
                        int* __restrict__ deg, int EA, int EB, int offB) {
    int i = blockIdx.x * blockDim.x + threadIdx.x;
    if (i < EA) atomicAdd(&deg[dstA[i]], 1);
    else if (i < EA + EB) atomicAdd(&deg[dstB[i - EA] + offB], 1);
}

// ---- two-level exclusive scan of (deg[i] + 1) -> rowptr ----
// scan1: per-block (1024 elems) local exclusive scan + block sum
__global__ void k_scan1(const int* __restrict__ deg, int* __restrict__ rowptr,
                        int* __restrict__ bsum, int n) {
    __shared__ int ss[1024];
    int tid = threadIdx.x;
    int i = blockIdx.x * 1024 + tid;
    int v = (i < n) ? deg[i] + 1 : 0;
    ss[tid] = v;
    __syncthreads();
    for (int d = 1; d < 1024; d <<= 1) {
        int t = (tid >= d) ? ss[tid - d] : 0;
        __syncthreads();
        ss[tid] += t;
        __syncthreads();
    }
    if (i < n) rowptr[i] = ss[tid] - v;       // exclusive within block
    if (tid == 1023) bsum[blockIdx.x] = ss[1023];
}
// scan2: single-block exclusive scan of block sums (nb <= 1024); writes rowptr[n]
__global__ void k_scan2(int* __restrict__ bsum, int* __restrict__ rowptr, int nb, int n) {
    __shared__ int ss[1024];
    int tid = threadIdx.x;
    int v = (tid < nb) ? bsum[tid] : 0;
    ss[tid] = v;
    __syncthreads();
    for (int d = 1; d < 1024; d <<= 1) {
        int t = (tid >= d) ? ss[tid - d] : 0;
        __syncthreads();
        ss[tid] += t;
        __syncthreads();
    }
    if (tid < nb) bsum[tid] = ss[tid] - v;    // exclusive block offsets
    if (tid == 1023) rowptr[n] = ss[1023];    // total
}
// scan3: add block offsets
__global__ void k_scan3(int* __restrict__ rowptr, const int* __restrict__ bsum, int n) {
    int i = blockIdx.x * 1024 + threadIdx.x;
    if (i < n) rowptr[i] += bsum[blockIdx.x];
}

// scatter edges + self loops; also emits the combined batch vector and the
// end-sentinel for the aggregate's branch-free over-read.
__global__ void k_scatter2(const int* __restrict__ srcA, const int* __restrict__ dstA,
                           const int* __restrict__ srcB, const int* __restrict__ dstB,
                           const int* __restrict__ rowptr, int* __restrict__ cursor,
                           int* __restrict__ outsrc,
                           const int* __restrict__ batA, const int* __restrict__ batB_in,
                           int* __restrict__ batout,
                           int EA, int EB, int offB, int Ncomb) {
    int i = blockIdx.x * blockDim.x + threadIdx.x;
    if (i >= EA + EB + Ncomb) return;
    if (i == 0) outsrc[EA + EB + Ncomb] = 0;   // sentinel (valid node id)
    int s, d;
    if (i < EA)            { s = srcA[i];            d = dstA[i]; }
    else if (i < EA + EB)  { int j = i - EA; s = srcB[j] + offB; d = dstB[j] + offB; }
    else {
        int n = i - EA - EB;                   // self loop for node n
        s = d = n;
        batout[n] = (n < offB) ? batA[n] : batB_in[n - offB] + BATCH;
    }
    int pos = rowptr[d] + atomicAdd(&cursor[d], 1);
    outsrc[pos] = s;
}

// ---------------- TF32 tensor-core GEMM, 3-stage cp.async pipeline ----------------
// MODE 1: C fp32, relu(.+bias). MODE 2: C fp16 (Ch) + fused ssrc/sdst dots.
// 128x128 CTA tile, 8 warps (2x4), warp tile 64x32, mma.sync m16n8k8 tf32.
// A smem [m][k] stride 20; B smem [k][n] stride 132. Raw fp32 bits as tf32.
template <int MODE>
__global__ void __launch_bounds__(256, 2) k_gemm(const float* __restrict__ A,
                                                 const float* __restrict__ W,
                                                 const float* __restrict__ bias,
                                                 float* __restrict__ C,
                                                 __half* __restrict__ Ch, int K,
                                                 const float* __restrict__ asrc,
                                                 const float* __restrict__ adst,
                                                 float* __restrict__ ssrc,
                                                 float* __restrict__ sdst) {
    __shared__ unsigned As[3][128][20];   // [m][k], pad 20
    __shared__ unsigned Bs[3][16][132];   // [k][n], pad 132
    int tid = threadIdx.x;
    int m0 = blockIdx.x * 128;
    int warp = tid >> 5, lane = tid & 31;
    int wm = (warp >> 2) << 6;   // 0 or 64
    int wn = (warp & 3) << 5;    // 0,32,64,96
    int qid = lane >> 2;         // 0..7
    int qlane = lane & 3;        // 0..3

    int a_row = tid >> 1, a_c8 = (tid & 1) << 3;
    int b_row = tid >> 4, b_c8 = (tid & 15) << 3;

    float acc[16][4];
#pragma unroll
    for (int i = 0; i < 16; i++)
#pragma unroll
        for (int j = 0; j < 4; j++) acc[i][j] = 0.f;

    int ntiles = K >> 4;

    // prologue: tiles 0,1 -> bufs 0,1
#pragma unroll
    for (int pt = 0; pt < 2; pt++) {
        if (pt < ntiles) {
            int k0 = pt << 4;
            const float* ga = &A[(size_t)(m0 + a_row) * K + k0 + a_c8];
            cp16(s2u(&As[pt][a_row][a_c8]), ga);
            cp16(s2u(&As[pt][a_row][a_c8 + 4]), ga + 4);
            const float* gb = &W[(size_t)(k0 + b_row) * 128 + b_c8];
            cp16(s2u(&Bs[pt][b_row][b_c8]), gb);
            cp16(s2u(&Bs[pt][b_row][b_c8 + 4]), gb + 4);
        }
        cp_commit();
    }

    for (int t = 0; t < ntiles; t++) {
        cp_wait1();          // tile t's copy complete (<=1 group pending)
        __syncthreads();     // also guards reuse of buf[(t+2)%3]
        int buf = t % 3;
        if (t + 2 < ntiles) {
            int nb = (t + 2) % 3;
            int k0 = (t + 2) << 4;
            const float* ga = &A[(size_t)(m0 + a_row) * K + k0 + a_c8];
            cp16(s2u(&As[nb][a_row][a_c8]), ga);
            cp16(s2u(&As[nb][a_row][a_c8 + 4]), ga + 4);
            const float* gb = &W[(size_t)(k0 + b_row) * 128 + b_c8];
            cp16(s2u(&Bs[nb][b_row][b_c8]), gb);
            cp16(s2u(&Bs[nb][b_row][b_c8 + 4]), gb + 4);
            cp_commit();
        } else {
            cp_commit();     // keep group count in step for wait_group 1
        }
#pragma unroll
        for (int ks = 0; ks < 2; ks++) {
            int kb = ks << 3;
            unsigned bf[4][2], af[4][4];
#pragma unroll
            for (int nt = 0; nt < 4; nt++) {
                int n = wn + (nt << 3) + qid;
                bf[nt][0] = Bs[buf][kb + qlane][n];
                bf[nt][1] = Bs[buf][kb + qlane + 4][n];
            }
#pragma unroll
            for (int mt = 0; mt < 4; mt++) {
                int m = wm + (mt << 4) + qid;
                af[mt][0] = As[buf][m][kb + qlane];
                af[mt][1] = As[buf][m + 8][kb + qlane];
                af[mt][2] = As[buf][m][kb + qlane + 4];
                af[mt][3] = As[buf][m + 8][kb + qlane + 4];
            }
#pragma unroll
            for (int mt = 0; mt < 4; mt++)
#pragma unroll
                for (int nt = 0; nt < 4; nt++)
                    mma_tf32(acc[mt * 4 + nt], af[mt], bf[nt]);
        }
    }

    // epilogue: store C (+ optional fused scores)
#pragma unroll
    for (int mt = 0; mt < 4; mt++) {
        float psrc0 = 0.f, psrc1 = 0.f, pdst0 = 0.f, pdst1 = 0.f;
#pragma unroll
        for (int nt = 0; nt < 4; nt++) {
            float* c = acc[mt * 4 + nt];
            int row0 = m0 + wm + (mt << 4) + qid;
            int col = wn + (nt << 3) + (qlane << 1);
            float b0 = 0.f, b1 = 0.f;
            if (MODE == 1) { b0 = bias[col]; b1 = bias[col + 1]; }
            float2 v0, v1;
            v0.x = c[0]; v0.y = c[1];
            v1.x = c[2]; v1.y = c[3];
            if (MODE == 1) {
                v0.x = fmaxf(v0.x + b0, 0.f); v0.y = fmaxf(v0.y + b1, 0.f);
                v1.x = fmaxf(v1.x + b0, 0.f); v1.y = fmaxf(v1.y + b1, 0.f);
            }
            if (MODE == 2) {
                float a0 = asrc[col], a1 = asrc[col + 1];
                float d0 = adst[col], d1 = adst[col + 1];
                psrc0 += v0.x * a0 + v0.y * a1;
                psrc1 += v1.x * a0 + v1.y * a1;
                pdst0 += v0.x * d0 + v0.y * d1;
                pdst1 += v1.x * d0 + v1.y * d1;
                // fp16 store for the aggregate gather
                __half2 h0 = __float22half2_rn(v0);
                __half2 h1 = __float22half2_rn(v1);
                *(__half2*)&Ch[(size_t)row0 * 128 + col] = h0;
                *(__half2*)&Ch[(size_t)(row0 + 8) * 128 + col] = h1;
            } else {
                *(float2*)&C[(size_t)row0 * 128 + col] = v0;
                *(float2*)&C[(size_t)(row0 + 8) * 128 + col] = v1;
            }
        }
        if (MODE == 2) {
            // reduce over qlane group (lanes qid*4 .. qid*4+3)
#pragma unroll
            for (int o = 2; o; o >>= 1) {
                psrc0 += __shfl_down_sync(0xffffffffu, psrc0, o, 4);
                psrc1 += __shfl_down_sync(0xffffffffu, psrc1, o, 4);
                pdst0 += __shfl_down_sync(0xffffffffu, pdst0, o, 4);
                pdst1 += __shfl_down_sync(0xffffffffu, pdst1, o, 4);
            }
            if (qlane == 0) {
                int row0 = m0 + wm + (mt << 4) + qid;
                int head = warp & 3;
                ssrc[row0 * 4 + head] = psrc0;
                sdst[row0 * 4 + head] = pdst0;
                ssrc[(row0 + 8) * 4 + head] = psrc1;
                sdst[(row0 + 8) * 4 + head] = pdst1;
            }
        }
    }
}

// ---------------- fused softmax + aggregate + bias + LN + relu + residual (+pool) ----------------
// One warp per node (R15 proven form). Branch-free inner loop: unconditional
// over-read prefetch (srcs padded + sentinel), fmaxf leaky-relu, unroll 2.
template <bool LAST>
__global__ void __launch_bounds__(256) k_aggregate(
        const __half* __restrict__ hp, const float* __restrict__ ssrc,
        const float* __restrict__ sdst, const int* __restrict__ rowptr,
        const int* __restrict__ srcs, const float* __restrict__ bias,
        const float* __restrict__ gam, const float* __restrict__ bet,
        float* __restrict__ h, const int* __restrict__ batch,
        float* __restrict__ pool, float* __restrict__ cnt, int N) {
    int gw = (blockIdx.x * blockDim.x + threadIdx.x) >> 5;
    int lane = threadIdx.x & 31;
    if (gw >= N) return;
    int hh = lane >> 3;                  // head of this lane's 4 columns
    float sd = __ldg(&sdst[gw * 4 + hh]);
    int e0 = rowptr[gw], e1 = rowptr[gw + 1];

    float z = 0.f;
    float4 acc = make_float4(0.f, 0.f, 0.f, 0.f);

    // branch-free depth-2 pipeline (degree >= 1 always; srcs[e1] is a valid
    // index: next node's first edge, or the end sentinel)
    int s_cur = __ldg(&srcs[e0]);
    float sv_cur = __ldg(&ssrc[s_cur * 4 + hh]);
    uint2 hv_cur = __ldg((const uint2*)(hp + (size_t)s_cur * HID + 4 * lane));

#pragma unroll 2
    for (int e = e0; e < e1; e++) {
        int s_nxt = __ldg(&srcs[e + 1]);                       // over-read safe
        float sv_nxt = __ldg(&ssrc[s_nxt * 4 + hh]);
        uint2 hv_nxt = __ldg((const uint2*)(hp + (size_t)s_nxt * HID + 4 * lane));

        float ev = sv_cur + sd;
        ev = fmaxf(ev, 0.2f * ev);               // leaky_relu, branch-free
        float p = __expf(ev);
        z += p;
        float2 f01 = __half22float2(*(const __half2*)&hv_cur.x);
        float2 f23 = __half22float2(*(const __half2*)&hv_cur.y);
        acc.x = fmaf(p, f01.x, acc.x);
        acc.y = fmaf(p, f01.y, acc.y);
        acc.z = fmaf(p, f23.x, acc.z);
        acc.w = fmaf(p, f23.y, acc.w);
        sv_cur = sv_nxt; hv_cur = hv_nxt; s_cur = s_nxt;
    }

    float inv = 1.f / z;
    int c0 = 4 * lane;
    float4 bs = *(const float4*)&bias[c0];
    float r[4];
    r[0] = acc.x * inv + bs.x;
    r[1] = acc.y * inv + bs.y;
    r[2] = acc.z * inv + bs.z;
    r[3] = acc.w * inv + bs.w;

    // layernorm across the row (warp-wide)
    float s = r[0] + r[1] + r[2] + r[3];
#pragma unroll
    for (int o = 16; o; o >>= 1) s += __shfl_xor_sync(0xffffffffu, s, o);
    float mu = s * (1.f / 128.f);
    float var = 0.f;
#pragma unroll
    for (int t = 0; t < 4; t++) { float d = r[t] - mu; var = fmaf(d, d, var); }
#pragma unroll
    for (int o = 16; o; o >>= 1) var += __shfl_xor_sync(0xffffffffu, var, o);
    float rinv = rsqrtf(var * (1.f / 128.f) + LN_EPS);

    float4 g4 = *(const float4*)&gam[c0];
    float4 b4 = *(const float4*)&bet[c0];
    float4 hv = *(const float4*)&h[(size_t)gw * HID + c0];
    float4 nh;
    nh.x = hv.x + fmaxf((r[0] - mu) * rinv * g4.x + b4.x, 0.f);
    nh.y = hv.y + fmaxf((r[1] - mu) * rinv * g4.y + b4.y, 0.f);
    nh.z = hv.z + fmaxf((r[2] - mu) * rinv * g4.z + b4.z, 0.f);
    nh.w = hv.w + fmaxf((r[3] - mu) * rinv * g4.w + b4.w, 0.f);
    *(float4*)&h[(size_t)gw * HID + c0] = nh;

    if (LAST) {
        int b = __ldg(&batch[gw]);
        float* pr = pool + (size_t)b * HID + c0;
        atomicAdd(pr + 0, nh.x);
        atomicAdd(pr + 1, nh.y);
        atomicAdd(pr + 2, nh.z);
        atomicAdd(pr + 3, nh.w);
        if (lane == 0) atomicAdd(&cnt[b], 1.f);
    }
}

// ---------------- MLP head: one block per batch row ----------------
__global__ void __launch_bounds__(128) k_mlp(const float* __restrict__ poolA, const float* __restrict__ cntA,
                                             const float* __restrict__ poolB, const float* __restrict__ cntB,
                                             const float* __restrict__ Wc1, const float* __restrict__ bc1,
                                             const float* __restrict__ Wc2, const float* __restrict__ bc2,
                                             const float* __restrict__ Wc3, const float* __restrict__ bc3,
                                             float* __restrict__ out) {
    __shared__ float z[256];
    __shared__ float o1[128];
    __shared__ float o2[64];
    int b = blockIdx.x, t = threadIdx.x;
    float ca = fmaxf(cntA[b], 1.f), cb = fmaxf(cntB[b], 1.f);
    z[t]       = poolA[(size_t)b * HID + t] / ca;
    z[t + 128] = poolB[(size_t)b * HID + t] / cb;
    __syncthreads();
    float a1 = bc1[t];
#pragma unroll 8
    for (int i = 0; i < 256; i++) a1 = fmaf(z[i], Wc1[i * 128 + t], a1);
    o1[t] = fmaxf(a1, 0.f);
    __syncthreads();
    if (t < 64) {
        float a2 = bc2[t];
#pragma unroll 8
        for (int i = 0; i < 128; i++) a2 = fmaf(o1[i], Wc2[i * 64 + t], a2);
        o2[t] = fmaxf(a2, 0.f);
    }
    __syncthreads();
    if (t < 32) {
        float a3 = fmaf(o2[t], Wc3[t], o2[t + 32] * Wc3[t + 32]);
#pragma unroll
        for (int o = 16; o; o >>= 1) a3 += __shfl_xor_sync(0xffffffffu, a3, o);
        if (t == 0) out[b] = 1.f / (1.f + __expf(-(a3 + bc3[0])));
    }
}

extern "C" void kernel_launch(void* const* d_in, const int* in_sizes, int n_in,
                              void* d_out, int out_size) {
    const float* tcr_x    = (const float*)d_in[0];
    const int*   tcr_ei   = (const int*)d_in[1];
    const int*   tcr_bat  = (const int*)d_in[2];
    const float* pep_x    = (const float*)d_in[3];
    const int*   pep_ei   = (const int*)d_in[4];
    const int*   pep_bat  = (const int*)d_in[5];
    const float* W_in     = (const float*)d_in[6];
    const float* b_in     = (const float*)d_in[7];
    const float* Wg       = (const float*)d_in[8];
    const float* bg       = (const float*)d_in[9];
    const float* att_src  = (const float*)d_in[10];
    const float* att_dst  = (const float*)d_in[11];
    const float* ln_g     = (const float*)d_in[12];
    const float* ln_b     = (const float*)d_in[13];
    const float* Wc1      = (const float*)d_in[14];
    const float* bc1      = (const float*)d_in[15];
    const float* Wc2      = (const float*)d_in[16];
    const float* bc2      = (const float*)d_in[17];
    const float* Wc3      = (const float*)d_in[18];
    const float* bc3      = (const float*)d_in[19];
    float* out = (float*)d_out;

    int Ntc = in_sizes[2];          // 131072
    int Etc = in_sizes[1] / 2;      // 2097152
    int Npp = in_sizes[5];          // 24576
    int Epp = in_sizes[4] / 2;      // 196608
    int Ncomb = Ntc + Npp;          // 155648

    float *hB, *ssrcB, *sdstB, *poolB, *cntB;
    __half* hpB;
    int *rpB, *curB, *ssB, *batB, *bsB;
    cudaGetSymbolAddress((void**)&hB, g_h);
    cudaGetSymbolAddress((void**)&hpB, g_hp);
    cudaGetSymbolAddress((void**)&ssrcB, g_ssrc);
    cudaGetSymbolAddress((void**)&sdstB, g_sdst);
    cudaGetSymbolAddress((void**)&rpB, g_rowptr);
    cudaGetSymbolAddress((void**)&curB, g_cursor);
    cudaGetSymbolAddress((void**)&ssB, g_srcsorted);
    cudaGetSymbolAddress((void**)&batB, g_batch);
    cudaGetSymbolAddress((void**)&bsB, g_bsum);
    cudaGetSymbolAddress((void**)&poolB, g_pool);
    cudaGetSymbolAddress((void**)&cntB, g_cnt);

    cudaMemsetAsync(poolB, 0, 2 * BATCH * HID * sizeof(float));
    cudaMemsetAsync(cntB, 0, 2 * BATCH * sizeof(float));

    // ---- combined CSR build (fused hist + two-level scan + fused scatter) ----
    cudaMemsetAsync(curB, 0, (size_t)Ncomb * sizeof(int));
    k_hist2<<<(Etc + Epp + 255) / 256, 256>>>(tcr_ei + Etc, pep_ei + Epp, curB, Etc, Epp, Ntc);
    int nbScan = (Ncomb + 1023) / 1024;
    k_scan1<<<nbScan, 1024>>>(curB, rpB, bsB, Ncomb);
    k_scan2<<<1, 1024>>>(bsB, rpB, nbScan, Ncomb);
    k_scan3<<<nbScan, 1024>>>(rpB, bsB, Ncomb);
    cudaMemsetAsync(curB, 0, (size_t)Ncomb * sizeof(int));
    k_scatter2<<<(Etc + Epp + Ncomb + 255) / 256, 256>>>(tcr_ei, tcr_ei + Etc,
                                                         pep_ei, pep_ei + Epp,
                                                         rpB, curB, ssB,
                                                         tcr_bat, pep_bat, batB,
                                                         Etc, Epp, Ntc, Ncomb);

    // ---- input projections (separate launches) ----
    k_gemm<1><<<Ntc / 128, 256>>>(tcr_x, W_in, b_in, hB, nullptr, D_IN,
                                  nullptr, nullptr, nullptr, nullptr);
    k_gemm<1><<<Npp / 128, 256>>>(pep_x, W_in, b_in, hB + (size_t)Ntc * HID, nullptr, D_IN,
                                  nullptr, nullptr, nullptr, nullptr);

    // ---- GAT layers on the combined graph ----
    for (int l = 0; l < NLAYERS; l++) {
        k_gemm<2><<<Ncomb / 128, 256>>>(hB, Wg + (size_t)l * HID * HID, nullptr,
                                        nullptr, hpB, HID,
                                        att_src + l * HID, att_dst + l * HID, ssrcB, sdstB);
        if (l == NLAYERS - 1)
            k_aggregate<true><<<Ncomb / 8, 256>>>(hpB, ssrcB, sdstB, rpB, ssB,
                                                  bg + l * HID, ln_g + l * HID, ln_b + l * HID,
                                                  hB, batB, poolB, cntB, Ncomb);
        else
            k_aggregate<false><<<Ncomb / 8, 256>>>(hpB, ssrcB, sdstB, rpB, ssB,
                                                   bg + l * HID, ln_g + l * HID, ln_b + l * HID,
                                                   hB, nullptr, nullptr, nullptr, Ncomb);
    }

    // ---- MLP head ----
    k_mlp<<<BATCH, 128>>>(poolB, cntB, poolB + BATCH * HID, cntB + BATCH,
                          Wc1, bc1, Wc2, bc2, Wc3, bc3, out);
}